// round 2
// baseline (speedup 1.0000x reference)
#include <cuda_runtime.h>
#include <math.h>

// Problem constants
#define B_ 256
#define T_ 128
#define D_ 256
#define U_ 512
#define G5 2560   // 5*U
#define G4 2048   // 4*U
#define G3 1536   // 3*U

// Scratch (device globals: allocation-free per harness rules)
__device__ float g_xg[B_ * T_ * G5];   // precomputed x@kernel + input_bias  (~335MB)
__device__ float g_h [B_ * U_];        // recurrent state h
__device__ float g_h1a[B_ * U_];       // ping
__device__ float g_h1b[B_ * U_];       // pong
__device__ float g_hl[B_ * U_];        // hl (4th recurrent gate chunk), used at step end

__device__ __forceinline__ float hsig(float x) {
    return fminf(fmaxf(0.2f * x + 0.5f, 0.0f), 1.0f);
}

// ---------------------------------------------------------------------------
// Init recurrent state from h0
// ---------------------------------------------------------------------------
__global__ void init_h_kernel(const float* __restrict__ h0) {
    int i = blockIdx.x * blockDim.x + threadIdx.x;
    if (i < B_ * U_) g_h[i] = h0[i];
}

// ---------------------------------------------------------------------------
// xg = x @ kernel + bias[0]
// X: (32768 x 256) row-major, W: (256 x 2560) row-major, out g_xg (32768 x 2560)
// Classic 128x128x8 SGEMM, 256 threads, 8x8 microtile.
// ---------------------------------------------------------------------------
__global__ void xg_gemm_kernel(const float* __restrict__ X,
                               const float* __restrict__ W,
                               const float* __restrict__ bias) {
    __shared__ float As[8 * 132];   // [k][m] padded
    __shared__ float Bs[8 * 128];   // [k][n]
    const int bm = blockIdx.y * 128;
    const int bn = blockIdx.x * 128;
    const int tid = threadIdx.x;
    const int tx = tid & 15, ty = tid >> 4;
    const int arow = tid >> 1, acol = (tid & 1) * 4;   // A tile 128x8
    const int brow = tid >> 5, bcol = (tid & 31) * 4;  // B tile 8x128

    float acc[8][8];
#pragma unroll
    for (int i = 0; i < 8; i++)
#pragma unroll
        for (int j = 0; j < 8; j++) acc[i][j] = 0.0f;

    const float* Xp = X + (bm + arow) * D_ + acol;
    const float* Wp = W + brow * G5 + bn + bcol;

    for (int k0 = 0; k0 < D_; k0 += 8) {
        float4 av = *(const float4*)(Xp + k0);
        As[(acol + 0) * 132 + arow] = av.x;
        As[(acol + 1) * 132 + arow] = av.y;
        As[(acol + 2) * 132 + arow] = av.z;
        As[(acol + 3) * 132 + arow] = av.w;
        *(float4*)&Bs[brow * 128 + bcol] = *(const float4*)(Wp + (long)k0 * G5);
        __syncthreads();
#pragma unroll
        for (int k = 0; k < 8; k++) {
            float a[8], b[8];
            *(float4*)(a)     = *(const float4*)&As[k * 132 + ty * 8];
            *(float4*)(a + 4) = *(const float4*)&As[k * 132 + ty * 8 + 4];
            *(float4*)(b)     = *(const float4*)&Bs[k * 128 + tx * 8];
            *(float4*)(b + 4) = *(const float4*)&Bs[k * 128 + tx * 8 + 4];
#pragma unroll
            for (int i = 0; i < 8; i++)
#pragma unroll
                for (int j = 0; j < 8; j++) acc[i][j] += a[i] * b[j];
        }
        __syncthreads();
    }

#pragma unroll
    for (int i = 0; i < 8; i++) {
        int m = bm + ty * 8 + i;
        float* o = g_xg + (long)m * G5 + bn + tx * 8;
#pragma unroll
        for (int j = 0; j < 8; j++) o[j] = acc[i][j] + bias[bn + tx * 8 + j];
    }
}

// ---------------------------------------------------------------------------
// Step kernel 1: hg = h @ Wr + rb, then GRU-style gates -> g_h1a, and store hl.
// Block computes a 64(m) x 16(u) tile of h1, with 4 gate columns fused.
// Grid: (U/16=32, B/64=4), 256 threads.
// ---------------------------------------------------------------------------
__global__ void step_rec_kernel(const float* __restrict__ Wr,
                                const float* __restrict__ bias, int t) {
    __shared__ float As[16 * 68];   // [k][m] padded
    __shared__ float Bs[16 * 64];   // [k][u*4 + gate]
    const int u0 = blockIdx.x * 16;
    const int m0 = blockIdx.y * 64;
    const int tid = threadIdx.x;
    const int tx = tid & 15, ty = tid >> 4;
    const int amm = tid >> 2, akk = (tid & 3) * 4;

    // Precompute B-loader coordinates (4 elements / thread, 16x64 tile)
    int bsmem[4]; long bglob[4];
#pragma unroll
    for (int r = 0; r < 4; r++) {
        int idx = tid + r * 256;
        int kk = idx >> 6, c = idx & 63;
        int gg = c >> 4, uu = c & 15;
        bsmem[r] = kk * 64 + uu * 4 + gg;
        bglob[r] = (long)kk * G4 + gg * U_ + u0 + uu;
    }

    float acc[4][4];
#pragma unroll
    for (int g = 0; g < 4; g++)
#pragma unroll
        for (int i = 0; i < 4; i++) acc[g][i] = 0.0f;

    const float* Ap = g_h + (m0 + amm) * U_ + akk;

    for (int k0 = 0; k0 < U_; k0 += 16) {
        float4 av = *(const float4*)(Ap + k0);
        As[(akk + 0) * 68 + amm] = av.x;
        As[(akk + 1) * 68 + amm] = av.y;
        As[(akk + 2) * 68 + amm] = av.z;
        As[(akk + 3) * 68 + amm] = av.w;
        const float* Wb = Wr + (long)k0 * G4;
#pragma unroll
        for (int r = 0; r < 4; r++) Bs[bsmem[r]] = Wb[bglob[r]];
        __syncthreads();
#pragma unroll
        for (int k = 0; k < 16; k++) {
            float a[4];
            *(float4*)a = *(const float4*)&As[k * 68 + ty * 4];
            float4 b = *(const float4*)&Bs[k * 64 + tx * 4];
#pragma unroll
            for (int i = 0; i < 4; i++) {
                acc[0][i] += a[i] * b.x;
                acc[1][i] += a[i] * b.y;
                acc[2][i] += a[i] * b.z;
                acc[3][i] += a[i] * b.w;
            }
        }
        __syncthreads();
    }

    const int u = u0 + tx;
    const float rb0 = bias[G5 + u];
    const float rb1 = bias[G5 + U_ + u];
    const float rb2 = bias[G5 + 2 * U_ + u];
    const float rb3 = bias[G5 + 3 * U_ + u];
#pragma unroll
    for (int i = 0; i < 4; i++) {
        int b = m0 + ty * 4 + i;
        const float* xg = g_xg + ((long)b * T_ + t) * G5;
        float z  = hsig(xg[u] + acc[0][i] + rb0);
        float r  = hsig(xg[U_ + u] + acc[1][i] + rb1);
        float hh = tanhf(xg[2 * U_ + u] + r * (acc[2][i] + rb2));
        float hold = g_h[b * U_ + u];
        g_h1a[b * U_ + u] = z * hold + (1.0f - z) * hh;
        g_hl[b * U_ + u]  = acc[3][i] + rb3;
    }
}

// ---------------------------------------------------------------------------
// Step kernel 2: tg = h1 @ Wt[i] + tb[i], gates -> new h1.
// phase 0: src=g_h1a, dst=g_h1b.  phase 1: src=g_h1b, final output (l gate,
// h_out -> g_h and d_out).
// Grid: (U/16=32, B/64=4), 256 threads.
// ---------------------------------------------------------------------------
__global__ void step_t_kernel(const float* __restrict__ Wt,
                              const float* __restrict__ tb,
                              float* __restrict__ out, int t, int phase) {
    __shared__ float As[16 * 68];
    __shared__ float Bs[16 * 64];   // 4th gate slot unused (padding)
    const int u0 = blockIdx.x * 16;
    const int m0 = blockIdx.y * 64;
    const int tid = threadIdx.x;
    const int tx = tid & 15, ty = tid >> 4;
    const int amm = tid >> 2, akk = (tid & 3) * 4;

    const float* src = (phase == 0) ? g_h1a : g_h1b;

    // B-loader: 16x48 tile, 3 elements/thread
    int bsmem[3]; long bglob[3];
#pragma unroll
    for (int r = 0; r < 3; r++) {
        int idx = tid + r * 256;
        int kk = idx / 48, c = idx % 48;
        int gg = c >> 4, uu = c & 15;
        bsmem[r] = kk * 64 + uu * 4 + gg;
        bglob[r] = (long)kk * G3 + gg * U_ + u0 + uu;
    }

    float acc[3][4];
#pragma unroll
    for (int g = 0; g < 3; g++)
#pragma unroll
        for (int i = 0; i < 4; i++) acc[g][i] = 0.0f;

    const float* Ap = src + (m0 + amm) * U_ + akk;

    for (int k0 = 0; k0 < U_; k0 += 16) {
        float4 av = *(const float4*)(Ap + k0);
        As[(akk + 0) * 68 + amm] = av.x;
        As[(akk + 1) * 68 + amm] = av.y;
        As[(akk + 2) * 68 + amm] = av.z;
        As[(akk + 3) * 68 + amm] = av.w;
        const float* Wb = Wt + (long)k0 * G3;
#pragma unroll
        for (int r = 0; r < 3; r++) Bs[bsmem[r]] = Wb[bglob[r]];
        __syncthreads();
#pragma unroll
        for (int k = 0; k < 16; k++) {
            float a[4];
            *(float4*)a = *(const float4*)&As[k * 68 + ty * 4];
            float4 b = *(const float4*)&Bs[k * 64 + tx * 4];
#pragma unroll
            for (int i = 0; i < 4; i++) {
                acc[0][i] += a[i] * b.x;
                acc[1][i] += a[i] * b.y;
                acc[2][i] += a[i] * b.z;
            }
        }
        __syncthreads();
    }

    const int u = u0 + tx;
    const float tb0 = tb[u];
    const float tb1 = tb[U_ + u];
    const float tb2 = tb[2 * U_ + u];
#pragma unroll
    for (int i = 0; i < 4; i++) {
        int b = m0 + ty * 4 + i;
        float zt = hsig(acc[0][i] + tb0);
        float rt = hsig(acc[1][i] + tb1);
        float ht = tanhf(rt * (acc[2][i] + tb2));
        float h1 = zt * src[b * U_ + u] + (1.0f - zt) * ht;
        if (phase == 0) {
            g_h1b[b * U_ + u] = h1;
        } else {
            const float* xg = g_xg + ((long)b * T_ + t) * G5;
            float l  = hsig(xg[3 * U_ + u] + g_hl[b * U_ + u]);
            float ho = l * h1 + (1.0f - l) * tanhf(xg[4 * U_ + u]);
            g_h[b * U_ + u] = ho;
            out[((long)b * T_ + t) * U_ + u] = ho;
        }
    }
}

// ---------------------------------------------------------------------------
extern "C" void kernel_launch(void* const* d_in, const int* in_sizes, int n_in,
                              void* d_out, int out_size) {
    (void)in_sizes; (void)n_in; (void)out_size;
    const float* x      = (const float*)d_in[0];
    const float* h0     = (const float*)d_in[1];
    const float* kernel = (const float*)d_in[2];
    const float* Wr     = (const float*)d_in[3];
    const float* Wt     = (const float*)d_in[4];   // (2, 512, 1536)
    const float* bias   = (const float*)d_in[5];   // (2, 2560)
    const float* tbias  = (const float*)d_in[6];   // (2, 1536)
    float* out = (float*)d_out;

    init_h_kernel<<<(B_ * U_ + 255) / 256, 256>>>(h0);
    xg_gemm_kernel<<<dim3(G5 / 128, (B_ * T_) / 128), 256>>>(x, kernel, bias);

    for (int t = 0; t < T_; t++) {
        step_rec_kernel<<<dim3(U_ / 16, B_ / 64), 256>>>(Wr, bias, t);
        step_t_kernel<<<dim3(U_ / 16, B_ / 64), 256>>>(Wt, tbias, out, t, 0);
        step_t_kernel<<<dim3(U_ / 16, B_ / 64), 256>>>(Wt + (long)U_ * G3,
                                                       tbias + G3, out, t, 1);
    }
}

// round 6
// speedup vs baseline: 2.2048x; 2.2048x over previous
#include <cuda_runtime.h>
#include <math.h>

// Problem constants
#define B_ 256
#define T_ 128
#define D_ 256
#define U_ 512
#define G5 2560   // 5*U
#define G4 2048   // 4*U
#define G3 1536   // 3*U

#define NBLK 128
#define NTHR 128
#define KT 32
#define ASL 36
#define BSL 36

// Scratch (device globals: allocation-free per harness rules)
__device__ float g_xg[(long)B_ * T_ * G5]; // precomputed x@kernel + input_bias
__device__ float g_h [B_ * U_];            // recurrent state h
__device__ float g_h1a[B_ * U_];           // ping
__device__ float g_h1b[B_ * U_];           // pong
__device__ unsigned g_bar_ctr;             // grid barrier counter

__device__ __forceinline__ float hsig(float x) {
    return fminf(fmaxf(0.2f * x + 0.5f, 0.0f), 1.0f);
}

// packed f32x2 helpers (Blackwell double-pumped fp32)
__device__ __forceinline__ unsigned long long pk(float x) {
    unsigned long long r;
    asm("mov.b64 %0, {%1, %1};" : "=l"(r) : "f"(x));
    return r;
}
__device__ __forceinline__ unsigned long long f2(unsigned long long a,
                                                 unsigned long long b,
                                                 unsigned long long c) {
    unsigned long long d;
    asm("fma.rn.f32x2 %0, %1, %2, %3;" : "=l"(d) : "l"(a), "l"(b), "l"(c));
    return d;
}
__device__ __forceinline__ float2 up(unsigned long long v) {
    float2 r;
    asm("mov.b64 {%0, %1}, %2;" : "=f"(r.x), "=f"(r.y) : "l"(v));
    return r;
}

// ---------------------------------------------------------------------------
__global__ void init_h_kernel(const float* __restrict__ h0) {
    int i = blockIdx.x * blockDim.x + threadIdx.x;
    if (i < B_ * U_) g_h[i] = h0[i];
    if (i == 0) g_bar_ctr = 0;
}

// ---------------------------------------------------------------------------
// xg = x @ kernel + bias[0]   (known-good from R2)
// ---------------------------------------------------------------------------
__global__ void xg_gemm_kernel(const float* __restrict__ X,
                               const float* __restrict__ W,
                               const float* __restrict__ bias) {
    __shared__ float As[8 * 132];
    __shared__ float Bs[8 * 128];
    const int bm = blockIdx.y * 128;
    const int bn = blockIdx.x * 128;
    const int tid = threadIdx.x;
    const int tx = tid & 15, ty = tid >> 4;
    const int arow = tid >> 1, acol = (tid & 1) * 4;
    const int brow = tid >> 5, bcol = (tid & 31) * 4;

    float acc[8][8];
#pragma unroll
    for (int i = 0; i < 8; i++)
#pragma unroll
        for (int j = 0; j < 8; j++) acc[i][j] = 0.0f;

    const float* Xp = X + (bm + arow) * D_ + acol;
    const float* Wp = W + brow * G5 + bn + bcol;

    for (int k0 = 0; k0 < D_; k0 += 8) {
        float4 av = *(const float4*)(Xp + k0);
        As[(acol + 0) * 132 + arow] = av.x;
        As[(acol + 1) * 132 + arow] = av.y;
        As[(acol + 2) * 132 + arow] = av.z;
        As[(acol + 3) * 132 + arow] = av.w;
        *(float4*)&Bs[brow * 128 + bcol] = *(const float4*)(Wp + (long)k0 * G5);
        __syncthreads();
#pragma unroll
        for (int k = 0; k < 8; k++) {
            float a[8], b[8];
            *(float4*)(a)     = *(const float4*)&As[k * 132 + ty * 8];
            *(float4*)(a + 4) = *(const float4*)&As[k * 132 + ty * 8 + 4];
            *(float4*)(b)     = *(const float4*)&Bs[k * 128 + tx * 8];
            *(float4*)(b + 4) = *(const float4*)&Bs[k * 128 + tx * 8 + 4];
#pragma unroll
            for (int i = 0; i < 8; i++)
#pragma unroll
                for (int j = 0; j < 8; j++) acc[i][j] += a[i] * b[j];
        }
        __syncthreads();
    }

#pragma unroll
    for (int i = 0; i < 8; i++) {
        int m = bm + ty * 8 + i;
        float* o = g_xg + (long)m * G5 + bn + tx * 8;
#pragma unroll
        for (int j = 0; j < 8; j++) o[j] = acc[i][j] + bias[bn + tx * 8 + j];
    }
}

// ---------------------------------------------------------------------------
// Grid-wide barrier: release-arrive + acquire-spin (CG grid.sync pattern).
// bar.sync cumulativity extends thread 0's acquire/release to the whole CTA.
// ---------------------------------------------------------------------------
__device__ __forceinline__ void grid_bar(unsigned target) {
    __syncthreads();
    if (threadIdx.x == 0) {
        asm volatile("red.release.gpu.global.add.u32 [%0], %1;"
                     :: "l"(&g_bar_ctr), "r"(1u) : "memory");
        unsigned v;
        do {
            asm volatile("ld.acquire.gpu.global.u32 %0, [%1];"
                         : "=r"(v) : "l"(&g_bar_ctr) : "memory");
        } while (v < target);
    }
    __syncthreads();
}

// ---------------------------------------------------------------------------
// Fused tile GEMM: block computes 32m x (G gates x 32u) of  Asrc @ W.
// Thread (mIdx = tid>>4, uIdx = tid&15) owns 4m x (G x 2u); acc packed f32x2
// over the u-pair.
// ---------------------------------------------------------------------------
template <int G>
__device__ __forceinline__ void mm_tile(float* As, float* Bs,
                                        const float* __restrict__ Asrc,
                                        const float* __restrict__ W, int ldw,
                                        int m0, int u0,
                                        unsigned long long* acc) {
    const int tid  = threadIdx.x;
    const int uIdx = tid & 15;
    const int mIdx = tid >> 4;
    const int mA   = tid >> 2;        // A loader: row 0..31
    const int kA   = (tid & 3) * 8;   // A loader: k offset 0/8/16/24

#pragma unroll
    for (int i = 0; i < 4 * G; i++) acc[i] = 0ull;

    // B loader coordinates: 2G float4 per thread, tile KT x (G x 32u)
    int  bso[2 * G];
    long bgo[2 * G];
#pragma unroll
    for (int r = 0; r < 2 * G; r++) {
        int fi  = tid + r * NTHR;
        int kk  = fi / (8 * G);
        int rem = fi - kk * 8 * G;
        int g   = rem >> 3;
        int u4  = (rem & 7) * 4;
        bso[r] = (kk * G + g) * BSL + u4;
        bgo[r] = (long)kk * ldw + g * U_ + u0 + u4;
    }
    const float* Ap = Asrc + (m0 + mA) * U_ + kA;

    // prefetch first tile
    float4 pa0 = __ldcg((const float4*)(Ap));
    float4 pa1 = __ldcg((const float4*)(Ap + 4));
    float4 pb[2 * G];
#pragma unroll
    for (int r = 0; r < 2 * G; r++)
        pb[r] = __ldg((const float4*)(W + bgo[r]));

    for (int k0 = 0; k0 < U_; k0 += KT) {
        __syncthreads();
        As[(kA + 0) * ASL + mA] = pa0.x;
        As[(kA + 1) * ASL + mA] = pa0.y;
        As[(kA + 2) * ASL + mA] = pa0.z;
        As[(kA + 3) * ASL + mA] = pa0.w;
        As[(kA + 4) * ASL + mA] = pa1.x;
        As[(kA + 5) * ASL + mA] = pa1.y;
        As[(kA + 6) * ASL + mA] = pa1.z;
        As[(kA + 7) * ASL + mA] = pa1.w;
#pragma unroll
        for (int r = 0; r < 2 * G; r++)
            *(float4*)(Bs + bso[r]) = pb[r];
        __syncthreads();
        if (k0 + KT < U_) {
            pa0 = __ldcg((const float4*)(Ap + k0 + KT));
            pa1 = __ldcg((const float4*)(Ap + k0 + KT + 4));
#pragma unroll
            for (int r = 0; r < 2 * G; r++)
                pb[r] = __ldg((const float4*)(W + (long)(k0 + KT) * ldw + bgo[r]));
        }
#pragma unroll 8
        for (int kk = 0; kk < KT; kk++) {
            float4 av = *(const float4*)(As + kk * ASL + 4 * mIdx);
            unsigned long long a0 = pk(av.x), a1 = pk(av.y);
            unsigned long long a2 = pk(av.z), a3 = pk(av.w);
            const float* Bk = Bs + kk * G * BSL + 2 * uIdx;
#pragma unroll
            for (int g = 0; g < G; g++) {
                unsigned long long bg = *(const unsigned long long*)(Bk + g * BSL);
                acc[g * 4 + 0] = f2(a0, bg, acc[g * 4 + 0]);
                acc[g * 4 + 1] = f2(a1, bg, acc[g * 4 + 1]);
                acc[g * 4 + 2] = f2(a2, bg, acc[g * 4 + 2]);
                acc[g * 4 + 3] = f2(a3, bg, acc[g * 4 + 3]);
            }
        }
    }
}

// ---------------------------------------------------------------------------
// Persistent scan kernel: 128 blocks x 128 threads, whole T=128 scan.
// ---------------------------------------------------------------------------
__global__ void __launch_bounds__(NTHR)
scan_kernel(const float* __restrict__ Wr, const float* __restrict__ Wt,
            const float* __restrict__ bias, const float* __restrict__ tbias,
            float* __restrict__ out) {
    __shared__ float As[KT * ASL];
    __shared__ float Bs[KT * 4 * BSL];

    const int u0   = (blockIdx.x & 15) * 32;
    const int m0   = (blockIdx.x >> 4) * 32;
    const int tid  = threadIdx.x;
    const int uIdx = tid & 15;
    const int mIdx = tid >> 4;

    unsigned barno = 0;
    unsigned long long acc[16];
    float h1r[4][2];   // h1 carried rec -> t0 -> t1 (own tile)
    float hlr[4][2];   // hl carried rec -> t1

    for (int t = 0; t < T_; t++) {
        // ---- phase REC: hg = h @ Wr (4 gates) ----
        mm_tile<4>(As, Bs, g_h, Wr, G4, m0, u0, acc);
#pragma unroll
        for (int i = 0; i < 4; i++) {
            const int b = m0 + mIdx * 4 + i;
            const float* xp = g_xg + ((long)b * T_ + t) * G5;
            float2 pz = up(acc[0 + i]), pr = up(acc[4 + i]);
            float2 ph = up(acc[8 + i]), pl = up(acc[12 + i]);
#pragma unroll
            for (int h2 = 0; h2 < 2; h2++) {
                const int u = u0 + uIdx * 2 + h2;
                float az = h2 ? pz.y : pz.x;
                float ar = h2 ? pr.y : pr.x;
                float ah = h2 ? ph.y : ph.x;
                float al = h2 ? pl.y : pl.x;
                float z  = hsig(__ldg(xp + u) + az + __ldg(bias + G5 + u));
                float r  = hsig(__ldg(xp + U_ + u) + ar + __ldg(bias + G5 + U_ + u));
                float hh = tanhf(__ldg(xp + 2 * U_ + u) +
                                 r * (ah + __ldg(bias + G5 + 2 * U_ + u)));
                float hold = __ldcg(g_h + (long)b * U_ + u);
                float h1 = z * hold + (1.0f - z) * hh;
                __stcg(g_h1a + (long)b * U_ + u, h1);
                h1r[i][h2] = h1;
                hlr[i][h2] = al + __ldg(bias + G5 + 3 * U_ + u);
            }
        }
        grid_bar(++barno * NBLK);

        // ---- phase T0: tg = h1 @ Wt[0] (3 gates) ----
        mm_tile<3>(As, Bs, g_h1a, Wt, G3, m0, u0, acc);
#pragma unroll
        for (int i = 0; i < 4; i++) {
            const int b = m0 + mIdx * 4 + i;
            float2 pz = up(acc[0 + i]), pr = up(acc[4 + i]), ph = up(acc[8 + i]);
#pragma unroll
            for (int h2 = 0; h2 < 2; h2++) {
                const int u = u0 + uIdx * 2 + h2;
                float az = h2 ? pz.y : pz.x;
                float ar = h2 ? pr.y : pr.x;
                float ah = h2 ? ph.y : ph.x;
                float zt = hsig(az + __ldg(tbias + u));
                float rt = hsig(ar + __ldg(tbias + U_ + u));
                float ht = tanhf(rt * (ah + __ldg(tbias + 2 * U_ + u)));
                float h1 = zt * h1r[i][h2] + (1.0f - zt) * ht;
                __stcg(g_h1b + (long)b * U_ + u, h1);
                h1r[i][h2] = h1;
            }
        }
        grid_bar(++barno * NBLK);

        // ---- phase T1: tg = h1 @ Wt[1] (3 gates), final combine ----
        mm_tile<3>(As, Bs, g_h1b, Wt + (long)U_ * G3, G3, m0, u0, acc);
#pragma unroll
        for (int i = 0; i < 4; i++) {
            const int b = m0 + mIdx * 4 + i;
            const float* xp = g_xg + ((long)b * T_ + t) * G5;
            float2 pz = up(acc[0 + i]), pr = up(acc[4 + i]), ph = up(acc[8 + i]);
#pragma unroll
            for (int h2 = 0; h2 < 2; h2++) {
                const int u = u0 + uIdx * 2 + h2;
                float az = h2 ? pz.y : pz.x;
                float ar = h2 ? pr.y : pr.x;
                float ah = h2 ? ph.y : ph.x;
                float zt = hsig(az + __ldg(tbias + G3 + u));
                float rt = hsig(ar + __ldg(tbias + G3 + U_ + u));
                float ht = tanhf(rt * (ah + __ldg(tbias + G3 + 2 * U_ + u)));
                float h1 = zt * h1r[i][h2] + (1.0f - zt) * ht;
                float l  = hsig(__ldg(xp + 3 * U_ + u) + hlr[i][h2]);
                float ho = l * h1 + (1.0f - l) * tanhf(__ldg(xp + 4 * U_ + u));
                __stcg(g_h + (long)b * U_ + u, ho);
                out[((long)b * T_ + t) * U_ + u] = ho;
            }
        }
        grid_bar(++barno * NBLK);
    }
}

// ---------------------------------------------------------------------------
extern "C" void kernel_launch(void* const* d_in, const int* in_sizes, int n_in,
                              void* d_out, int out_size) {
    (void)in_sizes; (void)n_in; (void)out_size;
    const float* x      = (const float*)d_in[0];
    const float* h0     = (const float*)d_in[1];
    const float* kernel = (const float*)d_in[2];
    const float* Wr     = (const float*)d_in[3];
    const float* Wt     = (const float*)d_in[4];   // (2, 512, 1536)
    const float* bias   = (const float*)d_in[5];   // (2, 2560)
    const float* tbias  = (const float*)d_in[6];   // (2, 1536)
    float* out = (float*)d_out;

    init_h_kernel<<<(B_ * U_ + 255) / 256, 256>>>(h0);
    xg_gemm_kernel<<<dim3(G5 / 128, (B_ * T_) / 128), 256>>>(x, kernel, bias);
    scan_kernel<<<NBLK, NTHR>>>(Wr, Wt, bias, tbias, out);
}